// round 6
// baseline (speedup 1.0000x reference)
#include <cuda_runtime.h>
#include <cuda_fp16.h>

#define NN 100000
#define EE 3200000
#define HH 8
#define CC 16
#define HC 128
#define PAD 128
#define LOG2E 1.4426950408889634f

// Scratch (__device__ globals -- no allocation allowed).
// One sentinel node slot (index NN): logit -1e30 -> weight 0, features 0.
__device__ __half g_h16[(NN + 1) * HC];   // projected features fp16
__device__ float  g_asrc[(NN + 1) * HH];  // src logits, premultiplied by log2(e)
__device__ float  g_adst[NN * HH];        // dst logits, premultiplied by log2(e)
__device__ int    g_deg[NN];              // in-degree (excl. self loop)
__device__ int    g_col[NN * PAD];        // padded CSR (src per edge, sentinel-padded)

struct alignas(8) H4 { __half2 a, b; };

#define PACK_F32X2(out, lo, hi) \
    asm("mov.b64 %0, {%1, %2};" : "=l"(out) : "f"(lo), "f"(hi))
#define UNPACK_F32X2(lo, hi, in) \
    asm("mov.b64 {%0, %1}, %2;" : "=f"(lo), "=f"(hi) : "l"(in))
#define FMA_F32X2(acc, a, b) \
    asm("fma.rn.f32x2 %0, %1, %2, %0;" : "+l"(acc) : "l"(a), "l"(b))

__device__ __forceinline__ float ex2f(float x) {
    float r; asm("ex2.approx.f32 %0, %1;" : "=f"(r) : "f"(x)); return r;
}

// ---------------- init: zero degree + sentinel node ----------------
__global__ void k_init(void) {
    int i = blockIdx.x * blockDim.x + threadIdx.x;
    if (i < NN) g_deg[i] = 0;
    if (i < HH) g_asrc[NN * HH + i] = -1e30f;
    if (i < HC / 2) ((__half2*)g_h16)[NN * (HC / 2) + i] = __floats2half2_rn(0.f, 0.f);
}

// ------- GEMM (FFMA2, 64-row blocks) + fused logits (prescaled by log2e) -------
__global__ void __launch_bounds__(256) k_gemm(const float* __restrict__ x,
                                              const float* __restrict__ W,
                                              const float* __restrict__ att_src,
                                              const float* __restrict__ att_dst) {
    __shared__ float sXT[32][66];   // [k][row], transposed, padded (8B-aligned rows)
    __shared__ float sW[32][HC];
    int tid = threadIdx.x, lane = tid & 31, wrp = tid >> 5;
    int rb = blockIdx.x * 64;
    int c = lane * 4, hh = lane >> 2;
    int r0 = wrp * 8;

    unsigned long long acc2[4][4];  // [row-pair][col]; f32x2 packed (row2p, row2p+1)
#pragma unroll
    for (int p = 0; p < 4; p++)
#pragma unroll
        for (int q = 0; q < 4; q++) acc2[p][q] = 0ull;

    for (int k0 = 0; k0 < 128; k0 += 32) {
        // stage x chunk (transposed)
#pragma unroll
        for (int s = 0; s < 2; s++) {
            int idx = tid + s * 256;
            int i = idx >> 3, j4 = idx & 7;
            int gr = rb + i;
            float4 v = make_float4(0.f, 0.f, 0.f, 0.f);
            if (gr < NN) v = *(const float4*)&x[gr * 128 + k0 + j4 * 4];
            sXT[j4 * 4 + 0][i] = v.x;
            sXT[j4 * 4 + 1][i] = v.y;
            sXT[j4 * 4 + 2][i] = v.z;
            sXT[j4 * 4 + 3][i] = v.w;
        }
        // stage W chunk
#pragma unroll
        for (int s = 0; s < 4; s++) {
            int idx = tid + s * 256;
            int i = idx >> 5, j4 = idx & 31;
            *(float4*)&sW[i][j4 * 4] = *(const float4*)&W[(k0 + i) * 128 + j4 * 4];
        }
        __syncthreads();
#pragma unroll
        for (int kk = 0; kk < 32; kk++) {
            float4 wv = *(const float4*)&sW[kk][c];
            unsigned long long w0, w1, w2, w3;
            PACK_F32X2(w0, wv.x, wv.x);
            PACK_F32X2(w1, wv.y, wv.y);
            PACK_F32X2(w2, wv.z, wv.z);
            PACK_F32X2(w3, wv.w, wv.w);
#pragma unroll
            for (int p = 0; p < 4; p++) {
                unsigned long long xp = *(const unsigned long long*)&sXT[kk][r0 + 2 * p];
                FMA_F32X2(acc2[p][0], xp, w0);
                FMA_F32X2(acc2[p][1], xp, w1);
                FMA_F32X2(acc2[p][2], xp, w2);
                FMA_F32X2(acc2[p][3], xp, w3);
            }
        }
        __syncthreads();
    }

    // epilogue: fp16 store + fused logits
    float4 av = *(const float4*)&att_src[hh * CC + (c & 15)];
    float4 dv = *(const float4*)&att_dst[hh * CC + (c & 15)];
#pragma unroll
    for (int p = 0; p < 4; p++) {
        float lo[4], hi[4];
#pragma unroll
        for (int q = 0; q < 4; q++) UNPACK_F32X2(lo[q], hi[q], acc2[p][q]);
#pragma unroll
        for (int half = 0; half < 2; half++) {
            float* f = half ? hi : lo;
            int gr = rb + r0 + 2 * p + half;
            bool ok = (gr < NN);
            if (ok) {
                H4 hv;
                hv.a = __floats2half2_rn(f[0], f[1]);
                hv.b = __floats2half2_rn(f[2], f[3]);
                *(H4*)&g_h16[gr * HC + c] = hv;
            }
            float s = f[0] * av.x + f[1] * av.y + f[2] * av.z + f[3] * av.w;
            float d = f[0] * dv.x + f[1] * dv.y + f[2] * dv.z + f[3] * dv.w;
            s += __shfl_xor_sync(0xffffffffu, s, 1);
            s += __shfl_xor_sync(0xffffffffu, s, 2);
            d += __shfl_xor_sync(0xffffffffu, d, 1);
            d += __shfl_xor_sync(0xffffffffu, d, 2);
            if (ok && (lane & 3) == 0) {
                g_asrc[gr * 8 + hh] = s * LOG2E;
                g_adst[gr * 8 + hh] = d * LOG2E;
            }
        }
    }
}

// ---------------- fill padded CSR in one pass ----------------
__global__ void k_fill(const int* __restrict__ ei) {
    int e = blockIdx.x * blockDim.x + threadIdx.x;
    if (e >= EE) return;
    int s = ei[e], d = ei[EE + e];
    int p = atomicAdd(&g_deg[d], 1);
    if (p < PAD) g_col[d * PAD + p] = s;
}

// ---------------- pad each node's list to a multiple of 8 with sentinel ----------------
__global__ void k_pad(void) {
    int i = blockIdx.x * blockDim.x + threadIdx.x;
    if (i >= NN) return;
    int d = g_deg[i]; if (d > PAD) d = PAD;
    int e = (d + 7) & ~7;
    for (int p = d; p < e; p++) g_col[i * PAD + p] = NN;
}

// ------- fused softmax + aggregation: warp/node, fp16 gather, no predication -------
__global__ void __launch_bounds__(256) k_agg(float* __restrict__ out,
                                             const float* __restrict__ bias) {
    int i = (blockIdx.x * blockDim.x + threadIdx.x) >> 5;
    if (i >= NN) return;
    int lane = threadIdx.x & 31;
    int hh = lane >> 2;

    float adv = g_adst[i * 8 + hh];

    // self loop (logits already in log2 domain)
    float t = g_asrc[i * 8 + hh] + adv;
    t = fmaxf(t, 0.2f * t);
    float w = ex2f(t);
    float wsum = w;
    H4 hv = *(const H4*)&g_h16[i * HC + lane * 4];
    float2 f0 = __half22float2(hv.a);
    float2 f1 = __half22float2(hv.b);
    float4 acc = make_float4(w * f0.x, w * f0.y, w * f1.x, w * f1.y);

    int deg = g_deg[i]; if (deg > PAD) deg = PAD;
    int degR = (deg + 7) & ~7;
    int beg = i * PAD, end = beg + degR;
    for (int e = beg; e < end; e += 8) {
        int4 ca = *(const int4*)&g_col[e];
        int4 cb = *(const int4*)&g_col[e + 4];
        int sj[8] = { ca.x, ca.y, ca.z, ca.w, cb.x, cb.y, cb.z, cb.w };
        float as8[8];
#pragma unroll
        for (int j = 0; j < 8; j++) as8[j] = g_asrc[sj[j] * 8 + hh];
        H4 hj[8];
#pragma unroll
        for (int j = 0; j < 8; j++) hj[j] = *(const H4*)&g_h16[sj[j] * HC + lane * 4];
#pragma unroll
        for (int j = 0; j < 8; j++) {
            float tj = as8[j] + adv;
            tj = fmaxf(tj, 0.2f * tj);
            float wj = ex2f(tj);
            wsum += wj;
            float2 g0 = __half22float2(hj[j].a);
            float2 g1 = __half22float2(hj[j].b);
            acc.x += wj * g0.x;
            acc.y += wj * g0.y;
            acc.z += wj * g1.x;
            acc.w += wj * g1.y;
        }
    }

    float inv = 1.f / (wsum + 1e-16f);
    float4 bv = *(const float4*)&bias[lane * 4];
    float4 o = make_float4(acc.x * inv + bv.x, acc.y * inv + bv.y,
                           acc.z * inv + bv.z, acc.w * inv + bv.w);
    *(float4*)&out[i * HC + lane * 4] = o;
}

extern "C" void kernel_launch(void* const* d_in, const int* in_sizes, int n_in,
                              void* d_out, int out_size) {
    const float* x    = (const float*)d_in[0];
    const int*   ei   = (const int*)d_in[1];
    const float* W    = (const float*)d_in[2];
    const float* as   = (const float*)d_in[3];
    const float* ad   = (const float*)d_in[4];
    const float* bias = (const float*)d_in[5];
    float* out = (float*)d_out;

    k_init <<<(NN + 255) / 256, 256>>>();
    k_gemm <<<(NN + 63) / 64, 256>>>(x, W, as, ad);
    k_fill <<<(EE + 255) / 256, 256>>>(ei);
    k_pad  <<<(NN + 255) / 256, 256>>>();
    k_agg  <<<(NN * 32 + 255) / 256, 256>>>(out, bias);
}

// round 7
// speedup vs baseline: 1.2374x; 1.2374x over previous
#include <cuda_runtime.h>
#include <cuda_fp16.h>

#define NN 100000
#define EE 3200000
#define HH 8
#define CC 16
#define HC 128
#define PAD 128
#define LOG2E 1.4426950408889634f

// Scratch (__device__ globals -- no allocation allowed).
// One sentinel node slot (index NN): logit -1e30 -> weight 0, features 0.
__device__ __half g_h16[(NN + 1) * HC];   // projected features fp16
__device__ float  g_asrc[(NN + 1) * HH];  // src logits, premultiplied by log2(e)
__device__ float  g_adst[NN * HH];        // dst logits, premultiplied by log2(e)
__device__ int    g_deg[NN];              // in-degree (excl. self loop)
__device__ int    g_col[NN * PAD];        // padded CSR (src per edge, sentinel-padded)

struct alignas(8) H4 { __half2 a, b; };

__device__ __forceinline__ float ex2f(float x) {
    float r; asm("ex2.approx.f32 %0, %1;" : "=f"(r) : "f"(x)); return r;
}

// ---------------- init: zero degree + sentinel node ----------------
__global__ void k_init(void) {
    int i = blockIdx.x * blockDim.x + threadIdx.x;
    if (i < NN) g_deg[i] = 0;
    if (i < HH) g_asrc[NN * HH + i] = -1e30f;
    if (i < HC / 2) ((__half2*)g_h16)[NN * (HC / 2) + i] = __floats2half2_rn(0.f, 0.f);
}

// ------- GEMM (proven R4 shape) + fused logits (prescaled by log2e) -------
__global__ void k_gemm(const float* __restrict__ x, const float* __restrict__ W,
                       const float* __restrict__ att_src, const float* __restrict__ att_dst) {
    __shared__ float sX[32][33];
    __shared__ float sW[32][HC];
    int tid = threadIdx.x;
    int lane = tid & 31;
    int rb = blockIdx.x * 32;
    int c = lane * 4;              // 4 contiguous output cols
    int r = (tid >> 5) * 4;        // 4 rows
    int hh = lane >> 2;            // head of this lane's cols
    float4 acc[4];
#pragma unroll
    for (int rr = 0; rr < 4; rr++) acc[rr] = make_float4(0.f, 0.f, 0.f, 0.f);

    for (int k0 = 0; k0 < 128; k0 += 32) {
        for (int idx = tid; idx < 32 * 32; idx += 256) {
            int i = idx >> 5, j = idx & 31;
            sX[i][j] = x[(rb + i) * 128 + k0 + j];
        }
        for (int idx = tid; idx < 32 * 128; idx += 256) {
            int i = idx >> 7, j = idx & 127;
            sW[i][j] = W[(k0 + i) * 128 + j];
        }
        __syncthreads();
#pragma unroll
        for (int kk = 0; kk < 32; kk++) {
            float4 wv = *(const float4*)&sW[kk][c];
#pragma unroll
            for (int rr = 0; rr < 4; rr++) {
                float xv = sX[r + rr][kk];
                acc[rr].x += xv * wv.x;
                acc[rr].y += xv * wv.y;
                acc[rr].z += xv * wv.z;
                acc[rr].w += xv * wv.w;
            }
        }
        __syncthreads();
    }

    // store fp16 features
#pragma unroll
    for (int rr = 0; rr < 4; rr++) {
        H4 hv;
        hv.a = __floats2half2_rn(acc[rr].x, acc[rr].y);
        hv.b = __floats2half2_rn(acc[rr].z, acc[rr].w);
        *(H4*)&g_h16[(rb + r + rr) * HC + c] = hv;
    }

    // fused attention logits: dot over this lane's 4 cols, reduce over the
    // 4 lanes (4k..4k+3) sharing head hh. Store in log2 domain.
    float4 av = *(const float4*)&att_src[hh * CC + (c & 15)];
    float4 dv = *(const float4*)&att_dst[hh * CC + (c & 15)];
#pragma unroll
    for (int rr = 0; rr < 4; rr++) {
        float s = acc[rr].x * av.x + acc[rr].y * av.y + acc[rr].z * av.z + acc[rr].w * av.w;
        float d = acc[rr].x * dv.x + acc[rr].y * dv.y + acc[rr].z * dv.z + acc[rr].w * dv.w;
        s += __shfl_xor_sync(0xffffffffu, s, 1);
        s += __shfl_xor_sync(0xffffffffu, s, 2);
        d += __shfl_xor_sync(0xffffffffu, d, 1);
        d += __shfl_xor_sync(0xffffffffu, d, 2);
        if ((lane & 3) == 0) {
            g_asrc[(rb + r + rr) * 8 + hh] = s * LOG2E;
            g_adst[(rb + r + rr) * 8 + hh] = d * LOG2E;
        }
    }
}

// ---------------- fill padded CSR in one pass ----------------
__global__ void k_fill(const int* __restrict__ ei) {
    int e = blockIdx.x * blockDim.x + threadIdx.x;
    if (e >= EE) return;
    int s = ei[e], d = ei[EE + e];
    int p = atomicAdd(&g_deg[d], 1);
    if (p < PAD) g_col[d * PAD + p] = s;
}

// ---------------- pad each node's list to a multiple of 8 with sentinel ----------------
__global__ void k_pad(void) {
    int i = blockIdx.x * blockDim.x + threadIdx.x;
    if (i >= NN) return;
    int d = g_deg[i]; if (d > PAD) d = PAD;
    int e = (d + 7) & ~7;
    for (int p = d; p < e; p++) g_col[i * PAD + p] = NN;
}

// ------- fused softmax + aggregation: warp/node, fp16 gather, no predication -------
__global__ void __launch_bounds__(256) k_agg(float* __restrict__ out,
                                             const float* __restrict__ bias) {
    int i = (blockIdx.x * blockDim.x + threadIdx.x) >> 5;
    if (i >= NN) return;
    int lane = threadIdx.x & 31;
    int hh = lane >> 2;

    float adv = g_adst[i * 8 + hh];

    // self loop (logits already in log2 domain)
    float t = g_asrc[i * 8 + hh] + adv;
    t = fmaxf(t, 0.2f * t);
    float w = ex2f(t);
    float wsum = w;
    H4 hv = *(const H4*)&g_h16[i * HC + lane * 4];
    float2 f0 = __half22float2(hv.a);
    float2 f1 = __half22float2(hv.b);
    float4 acc = make_float4(w * f0.x, w * f0.y, w * f1.x, w * f1.y);

    int deg = g_deg[i]; if (deg > PAD) deg = PAD;
    int degR = (deg + 7) & ~7;
    int beg = i * PAD, end = beg + degR;
    for (int e = beg; e < end; e += 8) {
        int4 ca = *(const int4*)&g_col[e];
        int4 cb = *(const int4*)&g_col[e + 4];
        int sj[8] = { ca.x, ca.y, ca.z, ca.w, cb.x, cb.y, cb.z, cb.w };
        float as8[8];
#pragma unroll
        for (int j = 0; j < 8; j++) as8[j] = g_asrc[sj[j] * 8 + hh];
        H4 hj[8];
#pragma unroll
        for (int j = 0; j < 8; j++) hj[j] = *(const H4*)&g_h16[sj[j] * HC + lane * 4];
#pragma unroll
        for (int j = 0; j < 8; j++) {
            float tj = as8[j] + adv;
            tj = fmaxf(tj, 0.2f * tj);
            float wj = ex2f(tj);
            wsum += wj;
            float2 g0 = __half22float2(hj[j].a);
            float2 g1 = __half22float2(hj[j].b);
            acc.x += wj * g0.x;
            acc.y += wj * g0.y;
            acc.z += wj * g1.x;
            acc.w += wj * g1.y;
        }
    }

    float inv = 1.f / (wsum + 1e-16f);
    float4 bv = *(const float4*)&bias[lane * 4];
    float4 o = make_float4(acc.x * inv + bv.x, acc.y * inv + bv.y,
                           acc.z * inv + bv.z, acc.w * inv + bv.w);
    *(float4*)&out[i * HC + lane * 4] = o;
}

extern "C" void kernel_launch(void* const* d_in, const int* in_sizes, int n_in,
                              void* d_out, int out_size) {
    const float* x    = (const float*)d_in[0];
    const int*   ei   = (const int*)d_in[1];
    const float* W    = (const float*)d_in[2];
    const float* as   = (const float*)d_in[3];
    const float* ad   = (const float*)d_in[4];
    const float* bias = (const float*)d_in[5];
    float* out = (float*)d_out;

    k_init <<<(NN + 255) / 256, 256>>>();
    k_gemm <<<NN / 32, 256>>>(x, W, as, ad);
    k_fill <<<(EE + 255) / 256, 256>>>(ei);
    k_pad  <<<(NN + 255) / 256, 256>>>();
    k_agg  <<<(NN * 32 + 255) / 256, 256>>>(out, bias);
}